// round 1
// baseline (speedup 1.0000x reference)
#include <cuda_runtime.h>

#define Cdim 768
#define CRdim 192
#define Bb 8
#define Nn 1024

// Scratch layout: gc | vbar_acc | ca_acc | ybar_acc | h_acc
__device__ __align__(16) float g_scr[4 * Bb * Cdim + Bb * CRdim];

#define S_GC 0
#define S_VB (Bb * Cdim)
#define S_CA (2 * Bb * Cdim)
#define S_YB (3 * Bb * Cdim)
#define S_H  (4 * Bb * Cdim)

// K1: gc[b,c] = mean_n x[b,n,c].  grid = B*16 chunks, 768 threads (one per channel).
__global__ void __launch_bounds__(768) k_gc(const float* __restrict__ x) {
    int b = blockIdx.x >> 4;
    int chunk = blockIdx.x & 15;
    int c = threadIdx.x;
    const float* p = x + ((size_t)b * Nn + (size_t)chunk * 64) * Cdim + c;
    float s = 0.f;
    #pragma unroll 8
    for (int n = 0; n < 64; n++) s += p[(size_t)n * Cdim];
    atomicAdd(&g_scr[S_GC + b * Cdim + c], s * (1.0f / Nn));
}

// K2: vbar = gc@Wv (cols 0..767) and h = gc@W1 (cols 768..959).
// grid (4 col-tiles x 8 k-tiles), 256 threads. One thread = one output column,
// 8 batch accumulators share each weight load (8x reuse).
__global__ void __launch_bounds__(256) k_gemm1(const float* __restrict__ Wv,
                                               const float* __restrict__ W1) {
    __shared__ float sg[Bb][96];
    int k0 = blockIdx.y * 96;
    for (int i = threadIdx.x; i < Bb * 96; i += 256)
        sg[i / 96][i % 96] = g_scr[S_GC + (i / 96) * Cdim + k0 + (i % 96)];
    __syncthreads();
    int col = blockIdx.x * 256 + threadIdx.x;
    if (col >= Cdim + CRdim) return;
    float acc[Bb];
    #pragma unroll
    for (int b = 0; b < Bb; b++) acc[b] = 0.f;
    if (col < Cdim) {
        const float* wp = Wv + (size_t)k0 * Cdim + col;
        for (int k = 0; k < 96; k++) {
            float w = wp[(size_t)k * Cdim];
            #pragma unroll
            for (int b = 0; b < Bb; b++) acc[b] += sg[b][k] * w;
        }
        #pragma unroll
        for (int b = 0; b < Bb; b++) atomicAdd(&g_scr[S_VB + b * Cdim + col], acc[b]);
    } else {
        int j = col - Cdim;
        const float* wp = W1 + (size_t)k0 * CRdim + j;
        for (int k = 0; k < 96; k++) {
            float w = wp[(size_t)k * CRdim];
            #pragma unroll
            for (int b = 0; b < Bb; b++) acc[b] += sg[b][k] * w;
        }
        #pragma unroll
        for (int b = 0; b < Bb; b++) atomicAdd(&g_scr[S_H + b * CRdim + j], acc[b]);
    }
}

// K3: ca_pre = relu(h + b1) @ W2.  grid (3 col-tiles x 4 k-tiles of 48), 256 threads.
__global__ void __launch_bounds__(256) k_gemm2(const float* __restrict__ W2,
                                               const float* __restrict__ b1) {
    __shared__ float sh[Bb][48];
    int j0 = blockIdx.y * 48;
    for (int i = threadIdx.x; i < Bb * 48; i += 256) {
        int b = i / 48, jj = i % 48;
        float v = g_scr[S_H + b * CRdim + j0 + jj] + b1[j0 + jj];
        sh[b][jj] = v > 0.f ? v : 0.f;
    }
    __syncthreads();
    int col = blockIdx.x * 256 + threadIdx.x;
    float acc[Bb];
    #pragma unroll
    for (int b = 0; b < Bb; b++) acc[b] = 0.f;
    const float* wp = W2 + (size_t)j0 * Cdim + col;
    for (int j = 0; j < 48; j++) {
        float w = wp[(size_t)j * Cdim];
        #pragma unroll
        for (int b = 0; b < Bb; b++) acc[b] += sh[b][j] * w;
    }
    #pragma unroll
    for (int b = 0; b < Bb; b++) atomicAdd(&g_scr[S_CA + b * Cdim + col], acc[b]);
}

// K4: ybar = ((vbar+bv) * sigmoid(ca+b2)) @ Wo.  grid (3 x 8), 256 threads.
__global__ void __launch_bounds__(256) k_gemm3(const float* __restrict__ Wo,
                                               const float* __restrict__ bv,
                                               const float* __restrict__ b2) {
    __shared__ float sy[Bb][96];
    int k0 = blockIdx.y * 96;
    for (int i = threadIdx.x; i < Bb * 96; i += 256) {
        int b = i / 96, kk = i % 96;
        int k = k0 + kk;
        float vb = g_scr[S_VB + b * Cdim + k] + bv[k];
        float cp = g_scr[S_CA + b * Cdim + k] + b2[k];
        float sig = 1.f / (1.f + __expf(-cp));
        sy[b][kk] = vb * sig;
    }
    __syncthreads();
    int col = blockIdx.x * 256 + threadIdx.x;
    float acc[Bb];
    #pragma unroll
    for (int b = 0; b < Bb; b++) acc[b] = 0.f;
    const float* wp = Wo + (size_t)k0 * Cdim + col;
    for (int k = 0; k < 96; k++) {
        float w = wp[(size_t)k * Cdim];
        #pragma unroll
        for (int b = 0; b < Bb; b++) acc[b] += sy[b][k] * w;
    }
    #pragma unroll
    for (int b = 0; b < Bb; b++) atomicAdd(&g_scr[S_YB + b * Cdim + col], acc[b]);
}

// K5: out[row,:] = LN(x[row,:] + ybar[b,:] + bo) * gamma + beta.
// One block per row, 192 threads, float4 path. x should be L2-resident from K1.
__global__ void __launch_bounds__(192) k_ln(const float* __restrict__ x,
                                            const float* __restrict__ bo,
                                            const float* __restrict__ gamma,
                                            const float* __restrict__ beta,
                                            float* __restrict__ out) {
    __shared__ float red[2][8];
    int row = blockIdx.x;
    int b = row >> 10;
    int t = threadIdx.x;
    float4 xv = reinterpret_cast<const float4*>(x + (size_t)row * Cdim)[t];
    float4 yv = reinterpret_cast<const float4*>(&g_scr[S_YB + b * Cdim])[t];
    float4 bo4 = reinterpret_cast<const float4*>(bo)[t];
    float v0 = xv.x + yv.x + bo4.x;
    float v1 = xv.y + yv.y + bo4.y;
    float v2 = xv.z + yv.z + bo4.z;
    float v3 = xv.w + yv.w + bo4.w;
    float s = v0 + v1 + v2 + v3;
    float q = v0 * v0 + v1 * v1 + v2 * v2 + v3 * v3;
    #pragma unroll
    for (int o = 16; o; o >>= 1) {
        s += __shfl_xor_sync(0xffffffff, s, o);
        q += __shfl_xor_sync(0xffffffff, q, o);
    }
    int w = t >> 5;
    if ((t & 31) == 0) { red[0][w] = s; red[1][w] = q; }
    __syncthreads();
    if (t < 32) {
        float ss = (t < 6) ? red[0][t] : 0.f;
        float qq = (t < 6) ? red[1][t] : 0.f;
        #pragma unroll
        for (int o = 4; o; o >>= 1) {
            ss += __shfl_xor_sync(0xffffffff, ss, o);
            qq += __shfl_xor_sync(0xffffffff, qq, o);
        }
        if (t == 0) { red[0][0] = ss; red[1][0] = qq; }
    }
    __syncthreads();
    float mean = red[0][0] * (1.0f / Cdim);
    float var = red[1][0] * (1.0f / Cdim) - mean * mean;
    float rstd = rsqrtf(var + 1e-5f);
    float4 g4 = reinterpret_cast<const float4*>(gamma)[t];
    float4 be4 = reinterpret_cast<const float4*>(beta)[t];
    float4 o4;
    o4.x = (v0 - mean) * rstd * g4.x + be4.x;
    o4.y = (v1 - mean) * rstd * g4.y + be4.y;
    o4.z = (v2 - mean) * rstd * g4.z + be4.z;
    o4.w = (v3 - mean) * rstd * g4.w + be4.w;
    reinterpret_cast<float4*>(out + (size_t)row * Cdim)[t] = o4;
}

extern "C" void kernel_launch(void* const* d_in, const int* in_sizes, int n_in,
                              void* d_out, int out_size) {
    const float* x     = (const float*)d_in[0];
    // d_in[1..4] = Wq, bq, Wk, bk — mathematically unused (softmax over
    // a constant-in-m score row is exactly uniform).
    const float* Wv    = (const float*)d_in[5];
    const float* bv    = (const float*)d_in[6];
    const float* W1    = (const float*)d_in[7];
    const float* b1    = (const float*)d_in[8];
    const float* W2    = (const float*)d_in[9];
    const float* b2    = (const float*)d_in[10];
    const float* Wo    = (const float*)d_in[11];
    const float* bo    = (const float*)d_in[12];
    const float* gamma = (const float*)d_in[13];
    const float* beta  = (const float*)d_in[14];
    float* out = (float*)d_out;

    void* scr = nullptr;
    cudaGetSymbolAddress(&scr, g_scr);
    cudaMemsetAsync(scr, 0, sizeof(float) * (4 * Bb * Cdim + Bb * CRdim), 0);

    k_gc<<<Bb * 16, 768>>>(x);
    k_gemm1<<<dim3(4, 8), 256>>>(Wv, W1);
    k_gemm2<<<dim3(3, 4), 256>>>(W2, b1);
    k_gemm3<<<dim3(3, 8), 256>>>(Wo, bv, b2);
    k_ln<<<Bb * Nn, 192>>>(x, bo, gamma, beta, out);
}

// round 2
// speedup vs baseline: 1.2426x; 1.2426x over previous
#include <cuda_runtime.h>

#define Cdim 768
#define CRdim 192
#define Bb 8
#define Nn 1024

// Scratch layout: gc | vbar_acc | ca_acc | ybar_acc | h_acc
__device__ __align__(16) float g_scr[4 * Bb * Cdim + Bb * CRdim];

#define S_GC 0
#define S_VB (Bb * Cdim)
#define S_CA (2 * Bb * Cdim)
#define S_YB (3 * Bb * Cdim)
#define S_H  (4 * Bb * Cdim)

// K1: gc[b,c] = mean_n x[b,n,c].  grid = B*16 chunks, 768 threads (one per channel).
__global__ void __launch_bounds__(768) k_gc(const float* __restrict__ x) {
    int b = blockIdx.x >> 4;
    int chunk = blockIdx.x & 15;
    int c = threadIdx.x;
    const float* p = x + ((size_t)b * Nn + (size_t)chunk * 64) * Cdim + c;
    float s = 0.f;
    #pragma unroll 8
    for (int n = 0; n < 64; n++) s += p[(size_t)n * Cdim];
    atomicAdd(&g_scr[S_GC + b * Cdim + c], s * (1.0f / Nn));
}

// K2: vbar = gc@Wv (cols 0..767) and h = gc@W1 (cols 768..959).
// grid (8 col-tiles of 128 x 24 k-tiles of 32), 128 threads.
// One thread = one output column, 8 batch accumulators share each weight load.
__global__ void __launch_bounds__(128) k_gemm1(const float* __restrict__ Wv,
                                               const float* __restrict__ W1) {
    __shared__ float sg[Bb][32];
    int k0 = blockIdx.y * 32;
    for (int i = threadIdx.x; i < Bb * 32; i += 128)
        sg[i >> 5][i & 31] = g_scr[S_GC + (i >> 5) * Cdim + k0 + (i & 31)];
    __syncthreads();
    int col = blockIdx.x * 128 + threadIdx.x;
    if (col >= Cdim + CRdim) return;
    float acc[Bb];
    #pragma unroll
    for (int b = 0; b < Bb; b++) acc[b] = 0.f;
    if (col < Cdim) {
        const float* wp = Wv + (size_t)k0 * Cdim + col;
        #pragma unroll
        for (int k = 0; k < 32; k++) {
            float w = wp[(size_t)k * Cdim];
            #pragma unroll
            for (int b = 0; b < Bb; b++) acc[b] += sg[b][k] * w;
        }
        #pragma unroll
        for (int b = 0; b < Bb; b++) atomicAdd(&g_scr[S_VB + b * Cdim + col], acc[b]);
    } else {
        int j = col - Cdim;
        const float* wp = W1 + (size_t)k0 * CRdim + j;
        #pragma unroll
        for (int k = 0; k < 32; k++) {
            float w = wp[(size_t)k * CRdim];
            #pragma unroll
            for (int b = 0; b < Bb; b++) acc[b] += sg[b][k] * w;
        }
        #pragma unroll
        for (int b = 0; b < Bb; b++) atomicAdd(&g_scr[S_H + b * CRdim + j], acc[b]);
    }
}

// K3: ca_pre = relu(h + b1) @ W2.  grid (6 col-tiles of 128 x 8 k-tiles of 24), 128 thr.
__global__ void __launch_bounds__(128) k_gemm2(const float* __restrict__ W2,
                                               const float* __restrict__ b1) {
    __shared__ float sh[Bb][24];
    int j0 = blockIdx.y * 24;
    for (int i = threadIdx.x; i < Bb * 24; i += 128) {
        int b = i / 24, jj = i % 24;
        float v = g_scr[S_H + b * CRdim + j0 + jj] + b1[j0 + jj];
        sh[b][jj] = v > 0.f ? v : 0.f;
    }
    __syncthreads();
    int col = blockIdx.x * 128 + threadIdx.x;
    float acc[Bb];
    #pragma unroll
    for (int b = 0; b < Bb; b++) acc[b] = 0.f;
    const float* wp = W2 + (size_t)j0 * Cdim + col;
    #pragma unroll
    for (int j = 0; j < 24; j++) {
        float w = wp[(size_t)j * Cdim];
        #pragma unroll
        for (int b = 0; b < Bb; b++) acc[b] += sh[b][j] * w;
    }
    #pragma unroll
    for (int b = 0; b < Bb; b++) atomicAdd(&g_scr[S_CA + b * Cdim + col], acc[b]);
}

// K4: ybar = ((vbar+bv) * sigmoid(ca+b2)) @ Wo.
// grid (6 col-tiles of 128 x 24 k-tiles of 32), 128 threads.
__global__ void __launch_bounds__(128) k_gemm3(const float* __restrict__ Wo,
                                               const float* __restrict__ bv,
                                               const float* __restrict__ b2) {
    __shared__ float sy[Bb][32];
    int k0 = blockIdx.y * 32;
    for (int i = threadIdx.x; i < Bb * 32; i += 128) {
        int b = i >> 5, kk = i & 31;
        int k = k0 + kk;
        float vb = g_scr[S_VB + b * Cdim + k] + bv[k];
        float cp = g_scr[S_CA + b * Cdim + k] + b2[k];
        float sig = 1.f / (1.f + __expf(-cp));
        sy[b][kk] = vb * sig;
    }
    __syncthreads();
    int col = blockIdx.x * 128 + threadIdx.x;
    float acc[Bb];
    #pragma unroll
    for (int b = 0; b < Bb; b++) acc[b] = 0.f;
    const float* wp = Wo + (size_t)k0 * Cdim + col;
    #pragma unroll
    for (int k = 0; k < 32; k++) {
        float w = wp[(size_t)k * Cdim];
        #pragma unroll
        for (int b = 0; b < Bb; b++) acc[b] += sy[b][k] * w;
    }
    #pragma unroll
    for (int b = 0; b < Bb; b++) atomicAdd(&g_scr[S_YB + b * Cdim + col], acc[b]);
}

// K5: out[row,:] = LN(x[row,:] + ybar[b,:] + bo) * gamma + beta.
// One block per row, 192 threads, float4 path. x should be L2-resident from K1.
__global__ void __launch_bounds__(192) k_ln(const float* __restrict__ x,
                                            const float* __restrict__ bo,
                                            const float* __restrict__ gamma,
                                            const float* __restrict__ beta,
                                            float* __restrict__ out) {
    __shared__ float red[2][8];
    int row = blockIdx.x;
    int b = row >> 10;
    int t = threadIdx.x;
    float4 xv = reinterpret_cast<const float4*>(x + (size_t)row * Cdim)[t];
    float4 yv = reinterpret_cast<const float4*>(&g_scr[S_YB + b * Cdim])[t];
    float4 bo4 = reinterpret_cast<const float4*>(bo)[t];
    float v0 = xv.x + yv.x + bo4.x;
    float v1 = xv.y + yv.y + bo4.y;
    float v2 = xv.z + yv.z + bo4.z;
    float v3 = xv.w + yv.w + bo4.w;
    float s = v0 + v1 + v2 + v3;
    float q = v0 * v0 + v1 * v1 + v2 * v2 + v3 * v3;
    #pragma unroll
    for (int o = 16; o; o >>= 1) {
        s += __shfl_xor_sync(0xffffffff, s, o);
        q += __shfl_xor_sync(0xffffffff, q, o);
    }
    int w = t >> 5;
    if ((t & 31) == 0) { red[0][w] = s; red[1][w] = q; }
    __syncthreads();
    if (t < 32) {
        float ss = (t < 6) ? red[0][t] : 0.f;
        float qq = (t < 6) ? red[1][t] : 0.f;
        #pragma unroll
        for (int o = 4; o; o >>= 1) {
            ss += __shfl_xor_sync(0xffffffff, ss, o);
            qq += __shfl_xor_sync(0xffffffff, qq, o);
        }
        if (t == 0) { red[0][0] = ss; red[1][0] = qq; }
    }
    __syncthreads();
    float mean = red[0][0] * (1.0f / Cdim);
    float var = red[1][0] * (1.0f / Cdim) - mean * mean;
    float rstd = rsqrtf(var + 1e-5f);
    float4 g4 = reinterpret_cast<const float4*>(gamma)[t];
    float4 be4 = reinterpret_cast<const float4*>(beta)[t];
    float4 o4;
    o4.x = (v0 - mean) * rstd * g4.x + be4.x;
    o4.y = (v1 - mean) * rstd * g4.y + be4.y;
    o4.z = (v2 - mean) * rstd * g4.z + be4.z;
    o4.w = (v3 - mean) * rstd * g4.w + be4.w;
    reinterpret_cast<float4*>(out + (size_t)row * Cdim)[t] = o4;
}

extern "C" void kernel_launch(void* const* d_in, const int* in_sizes, int n_in,
                              void* d_out, int out_size) {
    const float* x     = (const float*)d_in[0];
    // d_in[1..4] = Wq, bq, Wk, bk — mathematically unused (softmax over
    // a constant-in-m score row is exactly uniform).
    const float* Wv    = (const float*)d_in[5];
    const float* bv    = (const float*)d_in[6];
    const float* W1    = (const float*)d_in[7];
    const float* b1    = (const float*)d_in[8];
    const float* W2    = (const float*)d_in[9];
    const float* b2    = (const float*)d_in[10];
    const float* Wo    = (const float*)d_in[11];
    const float* bo    = (const float*)d_in[12];
    const float* gamma = (const float*)d_in[13];
    const float* beta  = (const float*)d_in[14];
    float* out = (float*)d_out;

    void* scr = nullptr;
    cudaGetSymbolAddress(&scr, g_scr);
    cudaMemsetAsync(scr, 0, sizeof(float) * (4 * Bb * Cdim + Bb * CRdim), 0);

    k_gc<<<Bb * 16, 768>>>(x);
    k_gemm1<<<dim3(8, 24), 128>>>(Wv, W1);
    k_gemm2<<<dim3(6, 8), 128>>>(W2, b1);
    k_gemm3<<<dim3(6, 24), 128>>>(Wo, bv, b2);
    k_ln<<<Bb * Nn, 192>>>(x, bo, gamma, beta, out);
}